// round 12
// baseline (speedup 1.0000x reference)
#include <cuda_runtime.h>
#include <cuda_fp16.h>
#include <cstdint>

#define N_NODES 10000
#define N_EDGES 320000
#define HID 64
#define NB 79
#define NPAD (NB * 128)          // 10112
#define NEG -3.0e38f
#define SPLIT_TILE 18432         // 128 rows * 144B padded row in smem
#define ROWB 144                 // smem operand row stride (64 fp16 + 16 pad)
#define ROWE 272                 // smem E-staging row stride bytes (256 + 16 pad)
#define NCT (NB * 4)             // 316 col-blocks of 32

// ---------------- static device scratch ----------------
__device__ int   d_src[N_EDGES];
__device__ int   d_dst[N_EDGES];
__device__ float d_hA[N_NODES * HID];
__device__ float d_hB[N_NODES * HID];
__device__ float d_agg[N_NODES * HID];
// fp16 operand planes (single-term)
__device__ __half d_Gs[NPAD * HID];
__device__ __half d_Hs[NPAD * HID];
// per (32-col-block, row) softmax partials + factors
__device__ float d_pm[(size_t)NCT * NPAD];
__device__ float d_ps[(size_t)NCT * NPAD];
__device__ float d_pf[(size_t)NCT * NPAD];
__device__ __half d_E[(size_t)N_NODES * N_NODES];  // 200 MB exp scratch

// ---------------- helpers ----------------
__device__ __forceinline__ uint32_t smem_u32(const void* p) {
    uint32_t a;
    asm("{ .reg .u64 t; cvta.to.shared.u64 t, %1; cvt.u32.u64 %0, t; }" : "=r"(a) : "l"(p));
    return a;
}
__device__ __forceinline__ void ldsm4(uint32_t* r, uint32_t a) {
    asm volatile("ldmatrix.sync.aligned.m8n8.x4.shared.b16 {%0,%1,%2,%3}, [%4];"
                 : "=r"(r[0]), "=r"(r[1]), "=r"(r[2]), "=r"(r[3]) : "r"(a));
}
__device__ __forceinline__ void mma16816(float* c, const uint32_t* a, uint32_t b0, uint32_t b1) {
    asm volatile("mma.sync.aligned.m16n8k16.row.col.f32.f16.f16.f32 "
                 "{%0,%1,%2,%3},{%4,%5,%6,%7},{%8,%9},{%0,%1,%2,%3};"
                 : "+f"(c[0]), "+f"(c[1]), "+f"(c[2]), "+f"(c[3])
                 : "r"(a[0]), "r"(a[1]), "r"(a[2]), "r"(a[3]), "r"(b0), "r"(b1));
}

// =====================================================================
// Launch 1: prep = edge convert (+width detect) | zero agg | node embed | zero plane tails
// =====================================================================
__global__ void prep_kernel(const unsigned* __restrict__ raw,
                            const float* __restrict__ x,
                            const float* __restrict__ Win,
                            const float* __restrict__ bin) {
    int b = blockIdx.x, tid = threadIdx.x;
    if (b < 1250) {
        __shared__ unsigned s_is64;
        if (tid < 32) {
            unsigned acc = 0;
            for (int i = tid; i < 2048; i += 32) acc |= raw[2 * i + 1];
#pragma unroll
            for (int o = 16; o; o >>= 1) acc |= __shfl_xor_sync(0xffffffffu, acc, o);
            if (tid == 0) s_is64 = (acc == 0) ? 1u : 0u;
        }
        __syncthreads();
        int e = b * 256 + tid;
        if (s_is64) {
            d_src[e] = (int)raw[2 * e];
            d_dst[e] = (int)raw[2 * (N_EDGES + e)];
        } else {
            d_src[e] = (int)raw[e];
            d_dst[e] = (int)raw[N_EDGES + e];
        }
    } else if (b < 3750) {
        int i = (b - 1250) * 256 + tid;
        d_agg[i] = 0.f;
    } else if (b < 6250) {
        int local = b - 3750;
        int sub = tid >> 6, h = tid & 63;
        int n = local * 4 + sub;
        __shared__ float xs[4][24];
        if (h < 24) xs[sub][h] = x[n * 24 + h];
        __syncthreads();
        float a = bin[h];
#pragma unroll
        for (int k = 0; k < 24; k++) a = fmaf(xs[sub][k], Win[k * HID + h], a);
        d_hA[n * HID + h] = a;
    } else {
        int s = b - 6250;                            // 0..1: zero rows [N_NODES, NPAD)
        __half* zb = (s == 0) ? d_Gs : d_Hs;
        uint4* p = (uint4*)(zb + (size_t)N_NODES * HID);
        for (int i = tid; i < (NPAD - N_NODES) * HID / 8; i += 256)
            p[i] = make_uint4(0, 0, 0, 0);
    }
}

// =====================================================================
// Launch 2/4: agg[dst] += relu(h[src] + edge_attr@We + be)
// =====================================================================
__global__ void edge_kernel(const float* __restrict__ eattr,
                            const float* __restrict__ We,
                            const float* __restrict__ be, int sel) {
    int idx = blockIdx.x * 256 + threadIdx.x;
    int e = idx >> 4;
    int c = (idx & 15) * 4;
    const float* hin = sel ? d_hB : d_hA;
    int s = d_src[e], d = d_dst[e];
    float2 a  = *(const float2*)(eattr + 2 * e);
    float4 h4 = *(const float4*)(hin + s * HID + c);
    float4 w0 = *(const float4*)(We + c);
    float4 w1 = *(const float4*)(We + HID + c);
    float4 b4 = *(const float4*)(be + c);
    float v0 = fmaxf(h4.x + fmaf(a.x, w0.x, fmaf(a.y, w1.x, b4.x)), 0.f);
    float v1 = fmaxf(h4.y + fmaf(a.x, w0.y, fmaf(a.y, w1.y, b4.y)), 0.f);
    float v2 = fmaxf(h4.z + fmaf(a.x, w0.z, fmaf(a.y, w1.z, b4.z)), 0.f);
    float v3 = fmaxf(h4.w + fmaf(a.x, w0.w, fmaf(a.y, w1.w, b4.w)), 0.f);
    asm volatile("red.global.add.v4.f32 [%0], {%1,%2,%3,%4};"
                 :: "l"(d_agg + d * HID + c), "f"(v0), "f"(v1), "f"(v2), "f"(v3) : "memory");
}

// =====================================================================
// Launch 3: layer-1 MLP (relu out) + re-zero agg
// =====================================================================
__global__ void mlp1_kernel(const float* __restrict__ W1, const float* __restrict__ b1,
                            const float* __restrict__ W2, const float* __restrict__ b2) {
    int n = blockIdx.x, h = threadIdx.x;
    __shared__ float zs[HID], ts[HID];
    zs[h] = d_hA[n * HID + h] + d_agg[n * HID + h];
    d_agg[n * HID + h] = 0.f;
    __syncthreads();
    float t = b1[h];
#pragma unroll 16
    for (int k = 0; k < HID; k++) t = fmaf(zs[k], W1[k * HID + h], t);
    ts[h] = fmaxf(t, 0.f);
    __syncthreads();
    float o = b2[h];
#pragma unroll 16
    for (int k = 0; k < HID; k++) o = fmaf(ts[k], W2[k * HID + h], o);
    d_hB[n * HID + h] = fmaxf(o, 0.f);
}

// =====================================================================
// Launch 5: layer-2 MLP + g = h@M + write fp16 operand planes
// =====================================================================
__global__ void mlp2_kernel(const float* __restrict__ W1, const float* __restrict__ b1,
                            const float* __restrict__ W2, const float* __restrict__ b2,
                            const float* __restrict__ M) {
    int n = blockIdx.x, h = threadIdx.x;
    __shared__ float zs[HID], ts[HID];
    zs[h] = d_hB[n * HID + h] + d_agg[n * HID + h];
    __syncthreads();
    float t = b1[h];
#pragma unroll 16
    for (int k = 0; k < HID; k++) t = fmaf(zs[k], W1[k * HID + h], t);
    ts[h] = fmaxf(t, 0.f);
    __syncthreads();
    float o = b2[h];
#pragma unroll 16
    for (int k = 0; k < HID; k++) o = fmaf(ts[k], W2[k * HID + h], o);
    __syncthreads();
    zs[h] = o;
    __syncthreads();
    float g = 0.f;
#pragma unroll 16
    for (int k = 0; k < HID; k++) g = fmaf(zs[k], M[k * HID + h], g);
    size_t off = (size_t)n * HID + h;
    d_Hs[off] = __float2half(o);
    d_Gs[off] = __float2half(g);
}

// =====================================================================
// Launch 6: E = exp(G@H^T - m_blk) via mma.sync fp16 + smem-staged coalesced store
// CTA: 128x128 tile, 8 warps (2m x 4n), each warp 64x32; 2 CTAs/SM
// =====================================================================
__global__ void __launch_bounds__(256, 2) gemm_kernel() {
    extern __shared__ char smem[];
    uint32_t sbase = smem_u32(smem);
    int tid = threadIdx.x;
    int wid = tid >> 5, lane = tid & 31;
    int i0 = blockIdx.y * 128, j0 = blockIdx.x * 128;

    // load 2 tiles (A = G, B = H), insert 16B/row pad
    {
        const uint4* gs = (const uint4*)d_Gs;
        const uint4* hs = (const uint4*)d_Hs;
        for (int t = tid; t < 2048; t += 256) {
            int s = t >> 10, o = t & 1023;
            int row = o >> 3, q = o & 7;
            uint4 v = (s == 0) ? gs[(size_t)(i0 + row) * 8 + q]
                               : hs[(size_t)(j0 + row) * 8 + q];
            *(uint4*)(smem + s * SPLIT_TILE + row * ROWB + q * 16) = v;
        }
    }
    __syncthreads();

    int wm = wid >> 2, wn = wid & 3;
    float acc[4][4][4];
#pragma unroll
    for (int a = 0; a < 4; a++)
#pragma unroll
        for (int b = 0; b < 4; b++)
#pragma unroll
            for (int c = 0; c < 4; c++) acc[a][b][c] = 0.f;

    uint32_t lrow = (lane & 15), lcol = (lane >> 4) * 16;
    int bg = lane >> 3, br = lane & 7;
    int b_noff = (bg >> 1) * 8 + br;
    int b_koff = (bg & 1) * 16;

    uint32_t abase = sbase + (wm * 64 + lrow) * ROWB + lcol;
    uint32_t bbase = sbase + SPLIT_TILE + (wn * 32 + b_noff) * ROWB + b_koff;

#pragma unroll
    for (int ks = 0; ks < 4; ks++) {
        uint32_t a[4][4];
#pragma unroll
        for (int mi = 0; mi < 4; mi++) ldsm4(a[mi], abase + mi * 16 * ROWB + ks * 32);
        uint32_t bfr[2][4];
#pragma unroll
        for (int bi = 0; bi < 2; bi++)
            ldsm4(bfr[bi], bbase + bi * 16 * ROWB + ks * 32);
#pragma unroll
        for (int mi = 0; mi < 4; mi++)
#pragma unroll
            for (int ni = 0; ni < 4; ni++) {
                int bi = ni >> 1, h = ni & 1;
                mma16816(acc[mi][ni], a[mi], bfr[bi][h * 2], bfr[bi][h * 2 + 1]);
            }
    }
    __syncthreads();          // operand smem dead; reuse as E staging + partials

    char*   est  = smem;                            // [128][ROWE]
    float2* part = (float2*)(smem + 128 * ROWE);    // unused, kept for layout clarity
    (void)part;

    // phase 1: exp -> smem staging (conflict-free) + (m,s) partials -> global
    int q = lane >> 2, t2 = (lane & 3) * 2;
    bool edge_j = (blockIdx.x == NB - 1);
    size_t pidx_base = (size_t)(blockIdx.x * 4 + wn) * NPAD + i0;

#pragma unroll
    for (int mi = 0; mi < 4; mi++) {
#pragma unroll
        for (int half = 0; half < 2; half++) {
            int rl = wm * 64 + mi * 16 + q + half * 8;
            int gr = i0 + rl;
            float m = NEG, ssum = 0.f;
#pragma unroll
            for (int ni = 0; ni < 4; ni++) {
                int cg = j0 + wn * 32 + ni * 8 + t2;
                if (!edge_j || (cg < N_NODES))
                    m = fmaxf(m, fmaxf(acc[mi][ni][half * 2], acc[mi][ni][half * 2 + 1]));
            }
#pragma unroll
            for (int off = 1; off < 4; off <<= 1)
                m = fmaxf(m, __shfl_xor_sync(0xffffffffu, m, off));
            if (m > NEG) {
#pragma unroll
                for (int ni = 0; ni < 4; ni++) {
                    int ct = wn * 32 + ni * 8 + t2;
                    int cg = j0 + ct;
                    if (!edge_j || (cg < N_NODES)) {
                        float e0 = __expf(acc[mi][ni][half * 2] - m);
                        float e1 = __expf(acc[mi][ni][half * 2 + 1] - m);
                        ssum += e0 + e1;
                        *(__half2*)(est + rl * ROWE + ct * 2) = __floats2half2_rn(e0, e1);
                    }
                }
            }
#pragma unroll
            for (int off = 1; off < 4; off <<= 1)
                ssum += __shfl_xor_sync(0xffffffffu, ssum, off);
            if ((lane & 3) == 0) {
                d_pm[pidx_base + rl] = m;
                d_ps[pidx_base + rl] = ssum;
            }
        }
    }
    __syncthreads();

    // phase 2: coalesced streaming store of the 128x128 fp16 tile (STG.128)
    // N_NODES % 8 == 0 -> uint4 never straddles the valid-column boundary
    for (int it = tid; it < 2048; it += 256) {
        int row = it >> 4, c16 = it & 15;
        int gr = i0 + row;
        int gc = j0 + c16 * 8;
        if (gr < N_NODES && gc + 8 <= N_NODES) {
            uint4 v = *(const uint4*)(est + row * ROWE + c16 * 16);
            __stcs((uint4*)(d_E + (size_t)gr * N_NODES + gc), v);
        }
    }
}

// =====================================================================
// Launch 7: combine 316 col-block partials per row -> factors f = exp(m_blk-m)*inv
// =====================================================================
__global__ void combine_kernel() {
    int r = blockIdx.x * 256 + threadIdx.x;
    if (r >= N_NODES) return;
    float m = NEG;
    for (int t = 0; t < NCT; t++)
        m = fmaxf(m, d_pm[(size_t)t * NPAD + r]);
    float s = 0.f;
    for (int t = 0; t < NCT; t++)
        s += d_ps[(size_t)t * NPAD + r] * __expf(d_pm[(size_t)t * NPAD + r] - m);
    float inv = 1.f / s;
    for (int t = 0; t < NCT; t++)
        d_pf[(size_t)t * NPAD + r] = __expf(d_pm[(size_t)t * NPAD + r] - m) * inv;
}

// =====================================================================
// Launch 8: out[i][j] = E[i][j] * f[j>>5][i]   (streaming loads/stores)
// =====================================================================
__global__ void finalize_kernel(float* __restrict__ out) {
    int i  = blockIdx.y;
    int j8 = (blockIdx.x * 256 + threadIdx.x) * 8;
    if (j8 >= N_NODES) return;
    float f = d_pf[(size_t)(j8 >> 5) * NPAD + i];
    uint4 e8 = __ldcs((const uint4*)(d_E + (size_t)i * N_NODES + j8));
    __half2 h0 = *(__half2*)&e8.x, h1 = *(__half2*)&e8.y;
    __half2 h2 = *(__half2*)&e8.z, h3 = *(__half2*)&e8.w;
    float2 f0 = __half22float2(h0), f1 = __half22float2(h1);
    float2 f2 = __half22float2(h2), f3 = __half22float2(h3);
    float* dst = out + (size_t)i * N_NODES + j8;
    __stcs((float4*)dst,       make_float4(f0.x * f, f0.y * f, f1.x * f, f1.y * f));
    __stcs((float4*)(dst + 4), make_float4(f2.x * f, f2.y * f, f3.x * f, f3.y * f));
}

extern "C" void kernel_launch(void* const* d_in, const int* in_sizes, int n_in,
                              void* d_out, int out_size) {
    const float*    x     = (const float*)d_in[0];
    const float*    eattr = (const float*)d_in[1];
    const unsigned* eidx  = (const unsigned*)d_in[2];
    const float*    Win   = (const float*)d_in[3];
    const float*    bin   = (const float*)d_in[4];
    const float*    We    = (const float*)d_in[5];
    const float*    be    = (const float*)d_in[6];
    const float*    W1    = (const float*)d_in[7];
    const float*    b1    = (const float*)d_in[8];
    const float*    W2    = (const float*)d_in[9];
    const float*    b2    = (const float*)d_in[10];
    const float*    M     = (const float*)d_in[11];
    float*          out   = (float*)d_out;

    const int GEMM_SMEM = 128 * ROWE + 4096;        // 38912 (>= 2*SPLIT_TILE=36864)
    cudaFuncSetAttribute(gemm_kernel, cudaFuncAttributeMaxDynamicSharedMemorySize, GEMM_SMEM);

    prep_kernel<<<6252, 256>>>(eidx, x, Win, bin);                     // #1
    edge_kernel<<<N_EDGES * 16 / 256, 256>>>(eattr, We, be, 0);        // #2
    mlp1_kernel<<<N_NODES, HID>>>(W1, b1, W2, b2);                     // #3
    edge_kernel<<<N_EDGES * 16 / 256, 256>>>(eattr, We, be, 1);        // #4
    mlp2_kernel<<<N_NODES, HID>>>(W1, b1, W2, b2, M);                  // #5
    dim3 ggrid(NB, NB);
    gemm_kernel<<<ggrid, 256, GEMM_SMEM>>>();                          // #6
    combine_kernel<<<(N_NODES + 255) / 256, 256>>>();                  // #7
    dim3 fgrid(5, N_NODES);
    finalize_kernel<<<fgrid, 256>>>(out);                              // #8
}